// round 7
// baseline (speedup 1.0000x reference)
#include <cuda_runtime.h>
#include <math.h>

// x:[32,512,56,56] f32, w1:[32,512], w2:[512,32]
// out = concat(scaled [32,512,56,56], comp [32,512])

#define B 32
#define C 512
#define CR 32
#define HW 3136
#define HW4 784
#define BC (B*C)            // 16384
#define HBC (BC/2)          // 8192
#define NTOT (B*C*HW)
#define N4 (NTOT/4)         // 12845056 float4s
#define HALF4 (N4/2)        // 6422528 (= 8192*784, channel-aligned)
#define APPLY_BLOCKS (HALF4/256)   // 25088 exactly
#define REDUCE_BLOCKS (HBC/8)      // 1024 blocks, 8 warps each, 2 bc per warp

__device__ float g_y[BC];
__device__ float g_gate[BC];

// ---------------------------------------------------------------------------
// Kernel 1: y[bc] = mean(x[bc,:]). One WARP per bc-PAIR (bc, bc+8192):
// two far-apart coalesced streams per warp (the pattern that pushed the
// apply kernel to ~7 TB/s). 48 independent LDG.128 per lane.
// ---------------------------------------------------------------------------
__global__ __launch_bounds__(256) void k_reduce_mean(const float* __restrict__ x) {
    const int warp = threadIdx.x >> 5;
    const int lane = threadIdx.x & 31;
    const int bc0 = blockIdx.x * 8 + warp;
    const float4* __restrict__ xp0 = reinterpret_cast<const float4*>(x) + (size_t)bc0 * HW4;
    const float4* __restrict__ xp1 = xp0 + (size_t)HBC * HW4;

    float s0 = 0.f, s1 = 0.f;
    int j = lane;
    #pragma unroll 6
    for (int k = 0; k < 24; k++, j += 32) {
        float4 a = __ldcs(&xp0[j]);
        float4 b = __ldcs(&xp1[j]);
        s0 += (a.x + a.y) + (a.z + a.w);
        s1 += (b.x + b.y) + (b.z + b.w);
    }
    if (lane < 16) {                       // 784 = 24*32 + 16
        float4 a = __ldcs(&xp0[768 + lane]);
        float4 b = __ldcs(&xp1[768 + lane]);
        s0 += (a.x + a.y) + (a.z + a.w);
        s1 += (b.x + b.y) + (b.z + b.w);
    }
    #pragma unroll
    for (int o = 16; o > 0; o >>= 1) {
        s0 += __shfl_xor_sync(0xFFFFFFFFu, s0, o);
        s1 += __shfl_xor_sync(0xFFFFFFFFu, s1, o);
    }
    if (lane == 0) {
        g_y[bc0]       = s0 * (1.0f / HW);
        g_y[bc0 + HBC] = s1 * (1.0f / HW);
    }
}

// ---------------------------------------------------------------------------
// Kernel 2 (fused MLP): one block per b, 512 threads.
// Phase 1: h[r]=relu(sum_c y[b][c]*w1[r][c]); 16 warps, 2 r's per warp.
// Phase 2: g[b][c]=sigmoid(sum_r h[r]*w2[c][r]); one thread per c.
//          comp[b][c]=y[b][c]*(1-g)  (gate constant over H,W).
// ---------------------------------------------------------------------------
__global__ __launch_bounds__(512) void k_mlp(const float* __restrict__ w1,
                                             const float* __restrict__ w2,
                                             float* __restrict__ comp_out) {
    __shared__ float y_s[C];
    __shared__ float h_s[CR];
    const int b = blockIdx.x;
    const int tid = threadIdx.x;

    y_s[tid] = g_y[b * C + tid];
    __syncthreads();

    const int warp = tid >> 5;
    const int lane = tid & 31;
    #pragma unroll
    for (int r2 = 0; r2 < 2; r2++) {
        const int r = warp * 2 + r2;
        const float* __restrict__ w1r = w1 + r * C;
        float acc = 0.f;
        #pragma unroll
        for (int c = lane; c < C; c += 32)
            acc += y_s[c] * w1r[c];
        #pragma unroll
        for (int o = 16; o > 0; o >>= 1)
            acc += __shfl_xor_sync(0xFFFFFFFFu, acc, o);
        if (lane == 0) h_s[r] = fmaxf(acc, 0.f);
    }
    __syncthreads();

    const int c = tid;
    const float4* __restrict__ w2c = reinterpret_cast<const float4*>(w2 + c * CR);
    float acc = 0.f;
    #pragma unroll
    for (int j = 0; j < 8; j++) {
        float4 w = w2c[j];
        acc += h_s[4*j+0] * w.x + h_s[4*j+1] * w.y + h_s[4*j+2] * w.z + h_s[4*j+3] * w.w;
    }
    const float g = 1.0f / (1.0f + expf(-acc));
    const int idx = b * C + c;
    g_gate[idx] = g;
    comp_out[idx] = y_s[c] * (1.0f - g);
}

// ---------------------------------------------------------------------------
// Kernel 3: scaled = x * gate[bc]. TWO fully-coalesced distant streams per
// thread (i and i+HALF4). Measured ~7 TB/s. Exact grid, streaming hints.
// ---------------------------------------------------------------------------
__global__ __launch_bounds__(256) void k_apply_gate(const float* __restrict__ x,
                                                    float* __restrict__ out) {
    const int i0 = blockIdx.x * 256 + threadIdx.x;
    const int i1 = i0 + HALF4;

    const float4* __restrict__ xp = reinterpret_cast<const float4*>(x);
    float4* __restrict__ op = reinterpret_cast<float4*>(out);

    const float g0 = __ldg(&g_gate[i0 / HW4]);
    const float g1 = __ldg(&g_gate[i1 / HW4]);

    float4 v0 = __ldcs(&xp[i0]);
    float4 v1 = __ldcs(&xp[i1]);
    v0.x *= g0; v0.y *= g0; v0.z *= g0; v0.w *= g0;
    v1.x *= g1; v1.y *= g1; v1.z *= g1; v1.w *= g1;
    __stcs(&op[i0], v0);
    __stcs(&op[i1], v1);
}

// ---------------------------------------------------------------------------
extern "C" void kernel_launch(void* const* d_in, const int* in_sizes, int n_in,
                              void* d_out, int out_size) {
    const float* x  = (const float*)d_in[0];
    const float* w1 = (const float*)d_in[1];
    const float* w2 = (const float*)d_in[2];
    float* out = (float*)d_out;

    float* scaled = out;
    float* comp   = out + NTOT;

    k_reduce_mean<<<REDUCE_BLOCKS, 256>>>(x);
    k_mlp<<<B, 512>>>(w1, w2, comp);
    k_apply_gate<<<APPLY_BLOCKS, 256>>>(x, scaled);
}